// round 7
// baseline (speedup 1.0000x reference)
#include <cuda_runtime.h>
#include <cuda_bf16.h>

#define NB_MAX    16
#define CDIM      256
#define GEM_EPSF  1e-6f
#define NORM_EPSF 1e-12f
#define CHUNK     32

// Scratch (allocation-free). Zeroed at module load; the fused finalize tail
// re-zeroes everything after use, so the invariant holds across graph replays.
__device__ float        g_sums[NB_MAX * CDIM];
__device__ float        g_counts[NB_MAX];
__device__ unsigned int g_ticket;

template <bool CUBE>
__device__ __forceinline__ float gem1(float x, float pv) {
    float v = fmaxf(x, GEM_EPSF);
    return CUBE ? v * v * v : powf(v, pv);
}

template <bool CUBE>
__device__ __forceinline__ void acc4(float4& acc, const float4& x, float pv) {
    acc.x += gem1<CUBE>(x.x, pv);
    acc.y += gem1<CUBE>(x.y, pv);
    acc.z += gem1<CUBE>(x.z, pv);
    acc.w += gem1<CUBE>(x.w, pv);
}

__device__ __forceinline__ void flush_acc(
    float* s_acc, float* s_cnt, int cur_b, int c4,
    float4& acc, int& cnt)
{
    float* dst = s_acc + cur_b * CDIM + 4 * c4;
    if (acc.x != 0.0f || acc.y != 0.0f || acc.z != 0.0f || acc.w != 0.0f) {
        atomicAdd(dst + 0, acc.x);
        atomicAdd(dst + 1, acc.y);
        atomicAdd(dst + 2, acc.z);
        atomicAdd(dst + 3, acc.w);
        acc = make_float4(0.f, 0.f, 0.f, 0.f);
    }
    if (c4 == 0 && cnt) atomicAdd(&s_cnt[cur_b], (float)cnt);
    cnt = 0;
}

// ---- Fast path: block's whole range is ONE segment (common case).
// Identical 8-wide LDG.128 body as the proven chunk loop, but with no bidx
// loads, no branches, pointer-stepped addresses, and unroll-2 so next
// iteration's loads issue while this one accumulates. ----
template <bool CUBE>
__device__ __forceinline__ void stream_range(
    const float4* __restrict__ feat4, int r0, int r1, int c4, int rg,
    float pv, float4& acc, int& cnt)
{
    // This thread handles rows r0+rg, r0+rg+4, ... (< r1)
    const int rstart = r0 + rg;
    if (rstart >= r1) { cnt = 0; return; }
    const int it = (r1 - rstart + 3) >> 2;      // rows this thread touches
    cnt = it;

    const float4* ptr = feat4 + (size_t)rstart * (CDIM / 4) + c4;
    const int nfull = it >> 3;                  // full 8-row groups

    #pragma unroll 2
    for (int g = 0; g < nfull; ++g) {
        float4 v[8];
        #pragma unroll
        for (int k = 0; k < 8; ++k) v[k] = ptr[k * 256];  // 4-row stride = 256 float4
        ptr += 2048;
        #pragma unroll
        for (int k = 0; k < 8; ++k) acc4<CUBE>(acc, v[k], pv);
    }
    const int rem = it & 7;
    for (int t = 0; t < rem; ++t) {
        float4 x = ptr[t * 256];
        acc4<CUBE>(acc, x, pv);
    }
}

// ---- Slow path: block range spans a batch boundary (rare). R4 code. ----
template <bool CUBE>
__device__ __forceinline__ void accum_range(
    const float4* __restrict__ feat4, const int* __restrict__ bidx,
    int r0, int r1, int c4, int rg, float pv, float* s_acc, float* s_cnt)
{
    float4 acc = make_float4(0.f, 0.f, 0.f, 0.f);
    int cnt = 0;
    int cur_b = bidx[r0];
    int r = r0;

    for (; r + CHUNK <= r1; r += CHUNK) {
        // sorted batch_idx: equal endpoints => whole chunk in one segment
        if (bidx[r] == cur_b && bidx[r + CHUNK - 1] == cur_b) {
            float4 v[8];
            #pragma unroll
            for (int k = 0; k < 8; ++k)
                v[k] = feat4[(size_t)(r + 4 * k + rg) * (CDIM / 4) + c4];
            #pragma unroll
            for (int k = 0; k < 8; ++k) acc4<CUBE>(acc, v[k], pv);
            cnt += 8;
        } else {
            for (int rr = r; rr < r + CHUNK; ++rr) {
                int b = bidx[rr];
                if (b != cur_b) {
                    flush_acc(s_acc, s_cnt, cur_b, c4, acc, cnt);
                    cur_b = b;
                }
                if (rg == (rr & 3)) {
                    float4 x = feat4[(size_t)rr * (CDIM / 4) + c4];
                    acc4<CUBE>(acc, x, pv);
                    ++cnt;
                }
            }
        }
    }
    for (; r < r1; ++r) {
        int b = bidx[r];
        if (b != cur_b) {
            flush_acc(s_acc, s_cnt, cur_b, c4, acc, cnt);
            cur_b = b;
        }
        if (rg == (r & 3)) {
            float4 x = feat4[(size_t)r * (CDIM / 4) + c4];
            acc4<CUBE>(acc, x, pv);
            ++cnt;
        }
    }
    flush_acc(s_acc, s_cnt, cur_b, c4, acc, cnt);
}

__global__ void __launch_bounds__(256, 4) mink_fused(
    const float4* __restrict__ feat4, const float* __restrict__ p,
    const int* __restrict__ bidx, float* __restrict__ out,
    int n, int rpb, int nb)
{
    __shared__ float s_acc[NB_MAX * CDIM];
    __shared__ float s_cnt[NB_MAX];
    __shared__ unsigned int s_last;
    __shared__ float s_red[8];

    const int tid = threadIdx.x;
    const int c4  = tid & 63;
    const int rg  = tid >> 6;

    #pragma unroll
    for (int k = tid; k < NB_MAX * CDIM; k += 256) s_acc[k] = 0.0f;
    if (tid < NB_MAX) s_cnt[tid] = 0.0f;
    __syncthreads();

    const float pv = p[0];
    const int r0 = (int)blockIdx.x * rpb;
    const int r1 = min(n, r0 + rpb);
    if (r0 < r1) {
        const int b_first = bidx[r0];
        const int b_last  = bidx[r1 - 1];
        if (b_first == b_last) {
            float4 acc = make_float4(0.f, 0.f, 0.f, 0.f);
            int cnt = 0;
            if (pv == 3.0f)
                stream_range<true >(feat4, r0, r1, c4, rg, pv, acc, cnt);
            else
                stream_range<false>(feat4, r0, r1, c4, rg, pv, acc, cnt);
            flush_acc(s_acc, s_cnt, b_first, c4, acc, cnt);
        } else {
            if (pv == 3.0f)
                accum_range<true >(feat4, bidx, r0, r1, c4, rg, pv, s_acc, s_cnt);
            else
                accum_range<false>(feat4, bidx, r0, r1, c4, rg, pv, s_acc, s_cnt);
        }
    }
    __syncthreads();

    // Block -> global (skip zero entries: most blocks touch 1-2 batches).
    #pragma unroll
    for (int b = 0; b < NB_MAX; ++b) {
        float v = s_acc[b * CDIM + tid];
        if (v != 0.0f) atomicAdd(&g_sums[b * CDIM + tid], v);
    }
    if (tid < NB_MAX && s_cnt[tid] != 0.0f) atomicAdd(&g_counts[tid], s_cnt[tid]);

    // ---- last-block finalize (threadFenceReduction pattern) ----
    __threadfence();                 // release: my global sums visible pre-ticket
    __syncthreads();
    if (tid == 0) {
        unsigned int t = atomicAdd(&g_ticket, 1u);
        s_last = (t == gridDim.x - 1) ? 1u : 0u;
    }
    __syncthreads();
    if (s_last == 0u) return;
    __threadfence();                 // acquire side

    const float invp = 1.0f / pv;
    const int lane = tid & 31, warp = tid >> 5;

    float sums[NB_MAX], cnts[NB_MAX];
    #pragma unroll
    for (int b = 0; b < NB_MAX; ++b)                  // MLP=16: all loads first
        sums[b] = __ldcg(&g_sums[b * CDIM + tid]);
    #pragma unroll
    for (int b = 0; b < NB_MAX; ++b)
        cnts[b] = (b < nb) ? __ldcg(&g_counts[b]) : 0.0f;

    #pragma unroll
    for (int b = 0; b < NB_MAX; ++b) {
        if (b >= nb) break;
        float c    = cnts[b];
        float mean = (c > 0.0f) ? sums[b] / c : 0.0f;
        float desc = powf(mean, invp);   // mean >= eps^p > 0 when c>0
        float sq   = desc * desc;
        #pragma unroll
        for (int m = 16; m > 0; m >>= 1)
            sq += __shfl_xor_sync(0xffffffffu, sq, m);
        if (lane == 0) s_red[warp] = sq;
        __syncthreads();
        float tot = s_red[0] + s_red[1] + s_red[2] + s_red[3]
                  + s_red[4] + s_red[5] + s_red[6] + s_red[7];
        out[b * CDIM + tid] = desc / fmaxf(sqrtf(tot), NORM_EPSF);
        __syncthreads();
    }

    // Reset scratch for the next call / graph replay.
    #pragma unroll
    for (int k = tid; k < NB_MAX * CDIM; k += 256) g_sums[k] = 0.0f;
    if (tid < NB_MAX) g_counts[tid] = 0.0f;
    if (tid == 0) g_ticket = 0u;
}

extern "C" void kernel_launch(void* const* d_in, const int* in_sizes, int n_in,
                              void* d_out, int out_size)
{
    const float4* feat4 = (const float4*)d_in[0];
    const float*  p     = (const float*)d_in[1];
    const int*    bidx  = (const int*)d_in[2];

    int n  = in_sizes[2];          // N voxels
    int nb = out_size / CDIM;      // B point clouds
    if (nb > NB_MAX) nb = NB_MAX;

    // ~4 waves at 4 blocks/SM (work-stealing absorbs CTA completion spread).
    const int target = 148 * 16;
    int rpb = (n + target - 1) / target;
    rpb = (rpb + CHUNK - 1) & ~(CHUNK - 1);
    if (rpb < CHUNK) rpb = CHUNK;
    int grid = (n + rpb - 1) / rpb;

    mink_fused<<<grid, 256>>>(feat4, p, bidx, (float*)d_out, n, rpb, nb);
}

// round 9
// speedup vs baseline: 1.0422x; 1.0422x over previous
#include <cuda_runtime.h>
#include <cuda_bf16.h>

#define NB_MAX    16
#define CDIM      256
#define GEM_EPSF  1e-6f
#define NORM_EPSF 1e-12f
#define CHUNK     32

// Scratch (allocation-free). Zeroed at module load; the fused finalize tail
// re-zeroes everything after use, so the invariant holds across graph replays.
__device__ float        g_sums[NB_MAX * CDIM];
__device__ float        g_counts[NB_MAX];
__device__ unsigned int g_ticket;

template <bool CUBE>
__device__ __forceinline__ float gem1(float x, float pv) {
    float v = fmaxf(x, GEM_EPSF);
    return CUBE ? v * v * v : powf(v, pv);
}

template <bool CUBE>
__device__ __forceinline__ void acc4(float4& acc, const float4& x, float pv) {
    acc.x += gem1<CUBE>(x.x, pv);
    acc.y += gem1<CUBE>(x.y, pv);
    acc.z += gem1<CUBE>(x.z, pv);
    acc.w += gem1<CUBE>(x.w, pv);
}

__device__ __forceinline__ void flush_acc(
    float* s_acc, float* s_cnt, int cur_b, int c4,
    float4& acc, int& cnt)
{
    float* dst = s_acc + cur_b * CDIM + 4 * c4;
    if (acc.x != 0.0f || acc.y != 0.0f || acc.z != 0.0f || acc.w != 0.0f) {
        atomicAdd(dst + 0, acc.x);
        atomicAdd(dst + 1, acc.y);
        atomicAdd(dst + 2, acc.z);
        atomicAdd(dst + 3, acc.w);
        acc = make_float4(0.f, 0.f, 0.f, 0.f);
    }
    if (c4 == 0 && cnt) atomicAdd(&s_cnt[cur_b], (float)cnt);
    cnt = 0;
}

// Core accumulation (proven codegen: 8 batched LDG.128 per chunk, MLP=8).
// Thread (rg = tid>>6, c4 = tid&63) owns channels 4*c4..4*c4+3 and rows
// congruent to rg mod 4.
template <bool CUBE>
__device__ __forceinline__ void accum_range(
    const float4* __restrict__ feat4, const int* __restrict__ bidx,
    int r0, int r1, int c4, int rg, float pv, float* s_acc, float* s_cnt)
{
    float4 acc = make_float4(0.f, 0.f, 0.f, 0.f);
    int cnt = 0;
    int cur_b = bidx[r0];
    int r = r0;

    for (; r + CHUNK <= r1; r += CHUNK) {
        // sorted batch_idx: equal endpoints => whole chunk in one segment
        if (bidx[r] == cur_b && bidx[r + CHUNK - 1] == cur_b) {
            float4 v[8];
            #pragma unroll
            for (int k = 0; k < 8; ++k)
                v[k] = feat4[(size_t)(r + 4 * k + rg) * (CDIM / 4) + c4];
            #pragma unroll
            for (int k = 0; k < 8; ++k) acc4<CUBE>(acc, v[k], pv);
            cnt += 8;   // rows handled by THIS thread in this chunk
        } else {
            // per-row slow path (uniform branch: depends only on shared bidx)
            for (int rr = r; rr < r + CHUNK; ++rr) {
                int b = bidx[rr];
                if (b != cur_b) {
                    flush_acc(s_acc, s_cnt, cur_b, c4, acc, cnt);
                    cur_b = b;
                }
                if (rg == (rr & 3)) {
                    float4 x = feat4[(size_t)rr * (CDIM / 4) + c4];
                    acc4<CUBE>(acc, x, pv);
                    ++cnt;
                }
            }
        }
    }
    for (; r < r1; ++r) {               // tail rows
        int b = bidx[r];
        if (b != cur_b) {
            flush_acc(s_acc, s_cnt, cur_b, c4, acc, cnt);
            cur_b = b;
        }
        if (rg == (r & 3)) {
            float4 x = feat4[(size_t)r * (CDIM / 4) + c4];
            acc4<CUBE>(acc, x, pv);
            ++cnt;
        }
    }
    flush_acc(s_acc, s_cnt, cur_b, c4, acc, cnt);
}

__global__ void __launch_bounds__(256, 4) mink_fused(
    const float4* __restrict__ feat4, const float* __restrict__ p,
    const int* __restrict__ bidx, float* __restrict__ out,
    int n, int rpb, int nb)
{
    __shared__ float s_acc[NB_MAX * CDIM];
    __shared__ float s_cnt[NB_MAX];
    __shared__ unsigned int s_last;
    __shared__ float s_red[8];

    const int tid = threadIdx.x;
    const int c4  = tid & 63;
    const int rg  = tid >> 6;

    #pragma unroll
    for (int k = tid; k < NB_MAX * CDIM; k += 256) s_acc[k] = 0.0f;
    if (tid < NB_MAX) s_cnt[tid] = 0.0f;
    __syncthreads();

    const float pv = p[0];
    const int r0 = (int)blockIdx.x * rpb;
    const int r1 = min(n, r0 + rpb);
    if (r0 < r1) {
        if (pv == 3.0f)
            accum_range<true >(feat4, bidx, r0, r1, c4, rg, pv, s_acc, s_cnt);
        else
            accum_range<false>(feat4, bidx, r0, r1, c4, rg, pv, s_acc, s_cnt);
    }
    __syncthreads();

    // Block -> global (skip zero entries: most blocks touch 1-2 batches).
    #pragma unroll
    for (int b = 0; b < NB_MAX; ++b) {
        float v = s_acc[b * CDIM + tid];
        if (v != 0.0f) atomicAdd(&g_sums[b * CDIM + tid], v);
    }
    if (tid < NB_MAX && s_cnt[tid] != 0.0f) atomicAdd(&g_counts[tid], s_cnt[tid]);

    // ---- last-block finalize (threadFenceReduction pattern) ----
    __threadfence();                 // release: my global sums visible pre-ticket
    __syncthreads();
    if (tid == 0) {
        unsigned int t = atomicAdd(&g_ticket, 1u);
        s_last = (t == gridDim.x - 1) ? 1u : 0u;
    }
    __syncthreads();
    if (s_last == 0u) return;
    __threadfence();                 // acquire side

    const float invp = 1.0f / pv;
    const int lane = tid & 31, warp = tid >> 5;

    float sums[NB_MAX], cnts[NB_MAX];
    #pragma unroll
    for (int b = 0; b < NB_MAX; ++b)                  // MLP=16: all loads first
        sums[b] = __ldcg(&g_sums[b * CDIM + tid]);
    #pragma unroll
    for (int b = 0; b < NB_MAX; ++b)
        cnts[b] = (b < nb) ? __ldcg(&g_counts[b]) : 0.0f;

    #pragma unroll
    for (int b = 0; b < NB_MAX; ++b) {
        if (b >= nb) break;
        float c    = cnts[b];
        float mean = (c > 0.0f) ? sums[b] / c : 0.0f;
        float desc = powf(mean, invp);   // mean >= eps^p > 0 when c>0
        float sq   = desc * desc;
        #pragma unroll
        for (int m = 16; m > 0; m >>= 1)
            sq += __shfl_xor_sync(0xffffffffu, sq, m);
        if (lane == 0) s_red[warp] = sq;
        __syncthreads();
        float tot = s_red[0] + s_red[1] + s_red[2] + s_red[3]
                  + s_red[4] + s_red[5] + s_red[6] + s_red[7];
        out[b * CDIM + tid] = desc / fmaxf(sqrtf(tot), NORM_EPSF);
        __syncthreads();
    }

    // Reset scratch for the next call / graph replay.
    #pragma unroll
    for (int k = tid; k < NB_MAX * CDIM; k += 256) g_sums[k] = 0.0f;
    if (tid < NB_MAX) g_counts[tid] = 0.0f;
    if (tid == 0) g_ticket = 0u;
}

extern "C" void kernel_launch(void* const* d_in, const int* in_sizes, int n_in,
                              void* d_out, int out_size)
{
    const float4* feat4 = (const float4*)d_in[0];
    const float*  p     = (const float*)d_in[1];
    const int*    bidx  = (const int*)d_in[2];

    int n  = in_sizes[2];          // N voxels
    int nb = out_size / CDIM;      // B point clouds
    if (nb > NB_MAX) nb = NB_MAX;

    // ~4 waves at 4 blocks/SM: work-stealing across waves absorbs the
    // per-CTA completion spread (L2-die variance) that a single wave pays
    // as a straggler tax. Rows/block rounded to CHUNK.
    const int target = 148 * 16;
    int rpb = (n + target - 1) / target;
    rpb = (rpb + CHUNK - 1) & ~(CHUNK - 1);
    if (rpb < CHUNK) rpb = CHUNK;
    int grid = (n + rpb - 1) / rpb;

    mink_fused<<<grid, 256>>>(feat4, p, bidx, (float*)d_out, n, rpb, nb);
}

// round 11
// speedup vs baseline: 1.0655x; 1.0223x over previous
#include <cuda_runtime.h>
#include <cuda_bf16.h>

#define NB_MAX    16
#define CDIM      256
#define GEM_EPSF  1e-6f
#define NORM_EPSF 1e-12f
#define CHUNK     32

// Scratch (allocation-free). Zeroed at module load; the fused finalize tail
// re-zeroes everything after use, so the invariant holds across graph replays.
__device__ float        g_sums[NB_MAX * CDIM];
__device__ float        g_counts[NB_MAX];
__device__ unsigned int g_ticket;

template <bool CUBE>
__device__ __forceinline__ float gem1(float x, float pv) {
    float v = fmaxf(x, GEM_EPSF);
    return CUBE ? v * v * v : powf(v, pv);
}

template <bool CUBE>
__device__ __forceinline__ void acc4(float4& acc, const float4& x, float pv) {
    acc.x += gem1<CUBE>(x.x, pv);
    acc.y += gem1<CUBE>(x.y, pv);
    acc.z += gem1<CUBE>(x.z, pv);
    acc.w += gem1<CUBE>(x.w, pv);
}

__device__ __forceinline__ void flush_acc(
    float* s_acc, float* s_cnt, int cur_b, int c4,
    float4& acc, int& cnt)
{
    float* dst = s_acc + cur_b * CDIM + 4 * c4;
    if (acc.x != 0.0f || acc.y != 0.0f || acc.z != 0.0f || acc.w != 0.0f) {
        atomicAdd(dst + 0, acc.x);
        atomicAdd(dst + 1, acc.y);
        atomicAdd(dst + 2, acc.z);
        atomicAdd(dst + 3, acc.w);
        acc = make_float4(0.f, 0.f, 0.f, 0.f);
    }
    if (c4 == 0 && cnt) atomicAdd(&s_cnt[cur_b], (float)cnt);
    cnt = 0;
}

// Core accumulation (proven codegen: 8 batched LDG.128 per chunk, MLP=8).
// Fast-path loads use __ldcs (evict-first streaming): the 1GB feature stream
// is read-once, so don't let it churn L2. Thread (rg = tid>>6, c4 = tid&63)
// owns channels 4*c4..4*c4+3 and rows congruent to rg mod 4.
template <bool CUBE>
__device__ __forceinline__ void accum_range(
    const float4* __restrict__ feat4, const int* __restrict__ bidx,
    int r0, int r1, int c4, int rg, float pv, float* s_acc, float* s_cnt)
{
    float4 acc = make_float4(0.f, 0.f, 0.f, 0.f);
    int cnt = 0;
    int cur_b = bidx[r0];
    int r = r0;

    for (; r + CHUNK <= r1; r += CHUNK) {
        // sorted batch_idx: equal endpoints => whole chunk in one segment
        if (bidx[r] == cur_b && bidx[r + CHUNK - 1] == cur_b) {
            float4 v[8];
            #pragma unroll
            for (int k = 0; k < 8; ++k)
                v[k] = __ldcs(feat4 + (size_t)(r + 4 * k + rg) * (CDIM / 4) + c4);
            #pragma unroll
            for (int k = 0; k < 8; ++k) acc4<CUBE>(acc, v[k], pv);
            cnt += 8;   // rows handled by THIS thread in this chunk
        } else {
            // per-row slow path (uniform branch: depends only on shared bidx)
            for (int rr = r; rr < r + CHUNK; ++rr) {
                int b = bidx[rr];
                if (b != cur_b) {
                    flush_acc(s_acc, s_cnt, cur_b, c4, acc, cnt);
                    cur_b = b;
                }
                if (rg == (rr & 3)) {
                    float4 x = feat4[(size_t)rr * (CDIM / 4) + c4];
                    acc4<CUBE>(acc, x, pv);
                    ++cnt;
                }
            }
        }
    }
    for (; r < r1; ++r) {               // tail rows
        int b = bidx[r];
        if (b != cur_b) {
            flush_acc(s_acc, s_cnt, cur_b, c4, acc, cnt);
            cur_b = b;
        }
        if (rg == (r & 3)) {
            float4 x = feat4[(size_t)r * (CDIM / 4) + c4];
            acc4<CUBE>(acc, x, pv);
            ++cnt;
        }
    }
    flush_acc(s_acc, s_cnt, cur_b, c4, acc, cnt);
}

__global__ void __launch_bounds__(256, 4) mink_fused(
    const float4* __restrict__ feat4, const float* __restrict__ p,
    const int* __restrict__ bidx, float* __restrict__ out,
    int n, int rpb, int nb)
{
    __shared__ float s_acc[NB_MAX * CDIM];
    __shared__ float s_cnt[NB_MAX];
    __shared__ unsigned int s_last;
    __shared__ float s_red[8];

    const int tid = threadIdx.x;
    const int c4  = tid & 63;
    const int rg  = tid >> 6;

    #pragma unroll
    for (int k = tid; k < NB_MAX * CDIM; k += 256) s_acc[k] = 0.0f;
    if (tid < NB_MAX) s_cnt[tid] = 0.0f;
    __syncthreads();

    const float pv = p[0];
    const int r0 = (int)blockIdx.x * rpb;
    const int r1 = min(n, r0 + rpb);
    if (r0 < r1) {
        if (pv == 3.0f)
            accum_range<true >(feat4, bidx, r0, r1, c4, rg, pv, s_acc, s_cnt);
        else
            accum_range<false>(feat4, bidx, r0, r1, c4, rg, pv, s_acc, s_cnt);
    }
    __syncthreads();

    // Block -> global (skip zero entries: most blocks touch 1-2 batches).
    #pragma unroll
    for (int b = 0; b < NB_MAX; ++b) {
        float v = s_acc[b * CDIM + tid];
        if (v != 0.0f) atomicAdd(&g_sums[b * CDIM + tid], v);
    }
    if (tid < NB_MAX && s_cnt[tid] != 0.0f) atomicAdd(&g_counts[tid], s_cnt[tid]);

    // ---- last-block finalize (threadFenceReduction pattern) ----
    __threadfence();                 // release: my global sums visible pre-ticket
    __syncthreads();
    if (tid == 0) {
        unsigned int t = atomicAdd(&g_ticket, 1u);
        s_last = (t == gridDim.x - 1) ? 1u : 0u;
    }
    __syncthreads();
    if (s_last == 0u) return;
    __threadfence();                 // acquire side

    const float invp = 1.0f / pv;
    const int lane = tid & 31, warp = tid >> 5;

    float sums[NB_MAX], cnts[NB_MAX];
    #pragma unroll
    for (int b = 0; b < NB_MAX; ++b)                  // MLP=16: all loads first
        sums[b] = __ldcg(&g_sums[b * CDIM + tid]);
    #pragma unroll
    for (int b = 0; b < NB_MAX; ++b)
        cnts[b] = (b < nb) ? __ldcg(&g_counts[b]) : 0.0f;

    #pragma unroll
    for (int b = 0; b < NB_MAX; ++b) {
        if (b >= nb) break;
        float c    = cnts[b];
        float mean = (c > 0.0f) ? sums[b] / c : 0.0f;
        float desc = powf(mean, invp);   // mean >= eps^p > 0 when c>0
        float sq   = desc * desc;
        #pragma unroll
        for (int m = 16; m > 0; m >>= 1)
            sq += __shfl_xor_sync(0xffffffffu, sq, m);
        if (lane == 0) s_red[warp] = sq;
        __syncthreads();
        float tot = s_red[0] + s_red[1] + s_red[2] + s_red[3]
                  + s_red[4] + s_red[5] + s_red[6] + s_red[7];
        out[b * CDIM + tid] = desc / fmaxf(sqrtf(tot), NORM_EPSF);
        __syncthreads();
    }

    // Reset scratch for the next call / graph replay.
    #pragma unroll
    for (int k = tid; k < NB_MAX * CDIM; k += 256) g_sums[k] = 0.0f;
    if (tid < NB_MAX) g_counts[tid] = 0.0f;
    if (tid == 0) g_ticket = 0u;
}

extern "C" void kernel_launch(void* const* d_in, const int* in_sizes, int n_in,
                              void* d_out, int out_size)
{
    const float4* feat4 = (const float4*)d_in[0];
    const float*  p     = (const float*)d_in[1];
    const int*    bidx  = (const int*)d_in[2];

    int n  = in_sizes[2];          // N voxels
    int nb = out_size / CDIM;      // B point clouds
    if (nb > NB_MAX) nb = NB_MAX;

    // ~4 waves at 4 blocks/SM: work-stealing across waves absorbs the
    // per-CTA completion spread (L2-die variance) that a single wave pays
    // as a straggler tax. Rows/block rounded to CHUNK.
    const int target = 148 * 16;
    int rpb = (n + target - 1) / target;
    rpb = (rpb + CHUNK - 1) & ~(CHUNK - 1);
    if (rpb < CHUNK) rpb = CHUNK;
    int grid = (n + rpb - 1) / rpb;

    mink_fused<<<grid, 256>>>(feat4, p, bidx, (float*)d_out, n, rpb, nb);
}

// round 12
// speedup vs baseline: 1.0841x; 1.0175x over previous
#include <cuda_runtime.h>
#include <cuda_bf16.h>

#define NB_MAX    16
#define CDIM      256
#define GEM_EPSF  1e-6f
#define NORM_EPSF 1e-12f
#define CHUNK     32

// Scratch (allocation-free). Zeroed at module load; the fused finalize tail
// re-zeroes everything after use, so the invariant holds across graph replays.
__device__ float        g_sums[NB_MAX * CDIM];
__device__ float        g_counts[NB_MAX];
__device__ unsigned int g_ticket;

template <bool CUBE>
__device__ __forceinline__ float gem1(float x, float pv) {
    float v = fmaxf(x, GEM_EPSF);
    return CUBE ? v * v * v : powf(v, pv);
}

template <bool CUBE>
__device__ __forceinline__ void acc4(float4& acc, const float4& x, float pv) {
    acc.x += gem1<CUBE>(x.x, pv);
    acc.y += gem1<CUBE>(x.y, pv);
    acc.z += gem1<CUBE>(x.z, pv);
    acc.w += gem1<CUBE>(x.w, pv);
}

__device__ __forceinline__ void flush_acc(
    float* s_acc, float* s_cnt, int cur_b, int c4,
    float4& acc, int& cnt)
{
    float* dst = s_acc + cur_b * CDIM + 4 * c4;
    if (acc.x != 0.0f || acc.y != 0.0f || acc.z != 0.0f || acc.w != 0.0f) {
        atomicAdd(dst + 0, acc.x);
        atomicAdd(dst + 1, acc.y);
        atomicAdd(dst + 2, acc.z);
        atomicAdd(dst + 3, acc.w);
        acc = make_float4(0.f, 0.f, 0.f, 0.f);
    }
    if (c4 == 0 && cnt) atomicAdd(&s_cnt[cur_b], (float)cnt);
    cnt = 0;
}

// Core accumulation (proven codegen: 8 batched LDG.128 per chunk, MLP=8).
// Fast-path loads use __ldcs (evict-first streaming): the 1GB feature stream
// is read-once, so don't let it churn L2. Thread (rg = tid>>6, c4 = tid&63)
// owns channels 4*c4..4*c4+3 and rows congruent to rg mod 4.
template <bool CUBE>
__device__ __forceinline__ void accum_range(
    const float4* __restrict__ feat4, const int* __restrict__ bidx,
    int r0, int r1, int c4, int rg, float pv, float* s_acc, float* s_cnt)
{
    float4 acc = make_float4(0.f, 0.f, 0.f, 0.f);
    int cnt = 0;
    int cur_b = bidx[r0];
    int r = r0;

    for (; r + CHUNK <= r1; r += CHUNK) {
        // sorted batch_idx: equal endpoints => whole chunk in one segment
        if (bidx[r] == cur_b && bidx[r + CHUNK - 1] == cur_b) {
            float4 v[8];
            #pragma unroll
            for (int k = 0; k < 8; ++k)
                v[k] = __ldcs(feat4 + (size_t)(r + 4 * k + rg) * (CDIM / 4) + c4);
            #pragma unroll
            for (int k = 0; k < 8; ++k) acc4<CUBE>(acc, v[k], pv);
            cnt += 8;   // rows handled by THIS thread in this chunk
        } else {
            // per-row slow path (uniform branch: depends only on shared bidx)
            for (int rr = r; rr < r + CHUNK; ++rr) {
                int b = bidx[rr];
                if (b != cur_b) {
                    flush_acc(s_acc, s_cnt, cur_b, c4, acc, cnt);
                    cur_b = b;
                }
                if (rg == (rr & 3)) {
                    float4 x = feat4[(size_t)rr * (CDIM / 4) + c4];
                    acc4<CUBE>(acc, x, pv);
                    ++cnt;
                }
            }
        }
    }
    for (; r < r1; ++r) {               // tail rows
        int b = bidx[r];
        if (b != cur_b) {
            flush_acc(s_acc, s_cnt, cur_b, c4, acc, cnt);
            cur_b = b;
        }
        if (rg == (r & 3)) {
            float4 x = feat4[(size_t)r * (CDIM / 4) + c4];
            acc4<CUBE>(acc, x, pv);
            ++cnt;
        }
    }
    flush_acc(s_acc, s_cnt, cur_b, c4, acc, cnt);
}

__global__ void __launch_bounds__(256, 4) mink_fused(
    const float4* __restrict__ feat4, const float* __restrict__ p,
    const int* __restrict__ bidx, float* __restrict__ out,
    int n, int rpb, int nb)
{
    __shared__ float s_acc[NB_MAX * CDIM];
    __shared__ float s_cnt[NB_MAX];
    __shared__ unsigned int s_last;
    __shared__ float s_red[8];

    const int tid = threadIdx.x;
    const int c4  = tid & 63;
    const int rg  = tid >> 6;

    #pragma unroll
    for (int k = tid; k < NB_MAX * CDIM; k += 256) s_acc[k] = 0.0f;
    if (tid < NB_MAX) s_cnt[tid] = 0.0f;
    __syncthreads();

    const float pv = p[0];
    const int r0 = (int)blockIdx.x * rpb;
    const int r1 = min(n, r0 + rpb);
    if (r0 < r1) {
        if (pv == 3.0f)
            accum_range<true >(feat4, bidx, r0, r1, c4, rg, pv, s_acc, s_cnt);
        else
            accum_range<false>(feat4, bidx, r0, r1, c4, rg, pv, s_acc, s_cnt);
    }
    __syncthreads();

    // Block -> global (skip zero entries: most blocks touch 1-2 batches).
    #pragma unroll
    for (int b = 0; b < NB_MAX; ++b) {
        float v = s_acc[b * CDIM + tid];
        if (v != 0.0f) atomicAdd(&g_sums[b * CDIM + tid], v);
    }
    if (tid < NB_MAX && s_cnt[tid] != 0.0f) atomicAdd(&g_counts[tid], s_cnt[tid]);

    // ---- last-block finalize (threadFenceReduction pattern) ----
    __threadfence();                 // release: my global sums visible pre-ticket
    __syncthreads();
    if (tid == 0) {
        unsigned int t = atomicAdd(&g_ticket, 1u);
        s_last = (t == gridDim.x - 1) ? 1u : 0u;
    }
    __syncthreads();
    if (s_last == 0u) return;
    __threadfence();                 // acquire side

    const float invp = 1.0f / pv;
    const int lane = tid & 31, warp = tid >> 5;

    float sums[NB_MAX], cnts[NB_MAX];
    #pragma unroll
    for (int b = 0; b < NB_MAX; ++b)                  // MLP=16: all loads first
        sums[b] = __ldcg(&g_sums[b * CDIM + tid]);
    #pragma unroll
    for (int b = 0; b < NB_MAX; ++b)
        cnts[b] = (b < nb) ? __ldcg(&g_counts[b]) : 0.0f;

    #pragma unroll
    for (int b = 0; b < NB_MAX; ++b) {
        if (b >= nb) break;
        float c    = cnts[b];
        float mean = (c > 0.0f) ? sums[b] / c : 0.0f;
        float desc = powf(mean, invp);   // mean >= eps^p > 0 when c>0
        float sq   = desc * desc;
        #pragma unroll
        for (int m = 16; m > 0; m >>= 1)
            sq += __shfl_xor_sync(0xffffffffu, sq, m);
        if (lane == 0) s_red[warp] = sq;
        __syncthreads();
        float tot = s_red[0] + s_red[1] + s_red[2] + s_red[3]
                  + s_red[4] + s_red[5] + s_red[6] + s_red[7];
        out[b * CDIM + tid] = desc / fmaxf(sqrtf(tot), NORM_EPSF);
        __syncthreads();
    }

    // Reset scratch for the next call / graph replay.
    #pragma unroll
    for (int k = tid; k < NB_MAX * CDIM; k += 256) g_sums[k] = 0.0f;
    if (tid < NB_MAX) g_counts[tid] = 0.0f;
    if (tid == 0) g_ticket = 0u;
}

extern "C" void kernel_launch(void* const* d_in, const int* in_sizes, int n_in,
                              void* d_out, int out_size)
{
    const float4* feat4 = (const float4*)d_in[0];
    const float*  p     = (const float*)d_in[1];
    const int*    bidx  = (const int*)d_in[2];

    int n  = in_sizes[2];          // N voxels
    int nb = out_size / CDIM;      // B point clouds
    if (nb > NB_MAX) nb = NB_MAX;

    // ~8 waves at 4 blocks/SM: finer work-stealing quantum shrinks the
    // last-wave straggler tail that gates the fused finalize. Rows/block
    // rounded to CHUNK.
    const int target = 148 * 32;
    int rpb = (n + target - 1) / target;
    rpb = (rpb + CHUNK - 1) & ~(CHUNK - 1);
    if (rpb < CHUNK) rpb = CHUNK;
    int grid = (n + rpb - 1) / rpb;

    mink_fused<<<grid, 256>>>(feat4, p, bidx, (float*)d_out, n, rpb, nb);
}